// round 3
// baseline (speedup 1.0000x reference)
#include <cuda_runtime.h>
#include <cstdint>

// ---------------- problem shapes (fixed by the dataset) ----------------
constexpr int B   = 8;
constexpr int C   = 19;
constexpr int H   = 512;
constexpr int W   = 1024;
constexpr int HW  = H * W;            // 524288 = 2^19
constexpr int NPIX = B * HW;          // 4194304
constexpr int Hh  = 128;
constexpr int Wh  = 256;
constexpr int HhWh = Hh * Wh;         // 32768
constexpr int NHEAT = B * HhWh;       // 262144
constexpr int NBOX = 8 * 64;          // 512

constexpr float OHEM_THRESH = 0.22314355513142097f;  // -log(0.8), rounds to f32
constexpr int   NBINS = 4096;
constexpr float BIN_SCALE = (float)NBINS / OHEM_THRESH;
constexpr float F32_TINY = 1.17549435e-38f;

// ---------------- device accumulators (no allocs allowed) ----------------
__device__ double             g_sum_hard;
__device__ unsigned long long g_cnt_hard;
__device__ unsigned long long g_cnt_valid;
__device__ double             g_hist_sum[NBINS];
__device__ unsigned int       g_hist_cnt[NBINS];
__device__ double             g_pos_loss;
__device__ double             g_neg_loss;
__device__ double             g_npos;
__device__ double             g_reg_sum;

// ---------------- init ----------------
__global__ void init_kernel() {
    int i = blockIdx.x * blockDim.x + threadIdx.x;
    if (i == 0) {
        g_sum_hard = 0.0; g_cnt_hard = 0ull; g_cnt_valid = 0ull;
        g_pos_loss = 0.0; g_neg_loss = 0.0; g_npos = 0.0; g_reg_sum = 0.0;
    }
    for (int b = i; b < NBINS; b += blockDim.x * gridDim.x) {
        g_hist_sum[b] = 0.0;
        g_hist_cnt[b] = 0u;
    }
}

// ---------------- OHEM: fused log-softmax CE + hard sum/count + rare histogram ----------------
__global__ __launch_bounds__(256) void ohem_kernel(
    const float* __restrict__ seg, const int* __restrict__ masks)
{
    int p = blockIdx.x * blockDim.x + threadIdx.x;

    float ce = 0.0f;
    bool valid = false;

    if (p < NPIX) {
        int b  = p >> 19;          // / HW
        int hw = p & (HW - 1);
        const float* base = seg + (size_t)b * C * HW + hw;

        int t = masks[p];
        valid = (t != 255);

        float v[C];
        #pragma unroll
        for (int c = 0; c < C; c++) v[c] = __ldg(base + (size_t)c * HW);

        float m = v[0];
        #pragma unroll
        for (int c = 1; c < C; c++) m = fmaxf(m, v[c]);

        float s = 0.0f;
        float xt = v[0];
        #pragma unroll
        for (int c = 0; c < C; c++) {
            s += __expf(v[c] - m);
            xt = (c == t) ? v[c] : xt;       // predicated select, no spill
        }
        ce = valid ? (m + __logf(s) - xt) : 0.0f;
    }

    bool hard = ce > OHEM_THRESH;            // invalid -> ce=0 -> not hard

    // rare path: ce <= THRESH goes to global histogram (expected ~handful of hits)
    if (p < NPIX && !hard) {
        int bin = (int)(ce * BIN_SCALE);
        bin = min(max(bin, 0), NBINS - 1);
        atomicAdd(&g_hist_cnt[bin], 1u);
        atomicAdd(&g_hist_sum[bin], (double)ce);
    }

    // block reduction of hard-sum / hard-count / valid-count
    float fs = hard ? ce : 0.0f;
    #pragma unroll
    for (int o = 16; o > 0; o >>= 1) fs += __shfl_xor_sync(0xffffffffu, fs, o);
    unsigned bh = __ballot_sync(0xffffffffu, hard);
    unsigned bv = __ballot_sync(0xffffffffu, valid);

    __shared__ float    s_sum[8];
    __shared__ unsigned s_hard[8];
    __shared__ unsigned s_val[8];
    int lane = threadIdx.x & 31, wid = threadIdx.x >> 5;
    if (lane == 0) { s_sum[wid] = fs; s_hard[wid] = __popc(bh); s_val[wid] = __popc(bv); }
    __syncthreads();
    if (threadIdx.x == 0) {
        double ts = 0.0; unsigned th = 0, tv = 0;
        #pragma unroll
        for (int i = 0; i < 8; i++) { ts += (double)s_sum[i]; th += s_hard[i]; tv += s_val[i]; }
        atomicAdd(&g_sum_hard, ts);
        atomicAdd(&g_cnt_hard, (unsigned long long)th);
        atomicAdd(&g_cnt_valid, (unsigned long long)tv);
    }
}

// ---------------- focal loss over heatmaps ----------------
__global__ __launch_bounds__(256) void focal_kernel(
    const float* __restrict__ pred, const float* __restrict__ tgt)
{
    int i = blockIdx.x * blockDim.x + threadIdx.x;
    float pl = 0.0f, nl = 0.0f, np = 0.0f;
    if (i < NHEAT) {
        float p = fmaxf(pred[i], F32_TINY);
        float t = tgt[i];
        if (t == 1.0f) {
            float om = 1.0f - p;
            pl = __logf(p) * om * om;
            np = 1.0f;
        } else {
            float omt = 1.0f - t;
            float w = omt * omt; w *= w;
            nl = __logf(1.0f - p + F32_TINY) * p * p * w;
        }
    }
    #pragma unroll
    for (int o = 16; o > 0; o >>= 1) {
        pl += __shfl_xor_sync(0xffffffffu, pl, o);
        nl += __shfl_xor_sync(0xffffffffu, nl, o);
        np += __shfl_xor_sync(0xffffffffu, np, o);
    }
    __shared__ float sp[8], sn[8], sc[8];
    int lane = threadIdx.x & 31, wid = threadIdx.x >> 5;
    if (lane == 0) { sp[wid] = pl; sn[wid] = nl; sc[wid] = np; }
    __syncthreads();
    if (threadIdx.x == 0) {
        double tp = 0, tn = 0, tc = 0;
        #pragma unroll
        for (int k = 0; k < 8; k++) { tp += (double)sp[k]; tn += (double)sn[k]; tc += (double)sc[k]; }
        atomicAdd(&g_pos_loss, tp);
        atomicAdd(&g_neg_loss, tn);
        atomicAdd(&g_npos, tc);
    }
}

// ---------------- L1 regression over 512 boxes (single block) ----------------
__global__ __launch_bounds__(512) void reg_kernel(
    const float* __restrict__ wh, const float* __restrict__ bboxes,
    const int* __restrict__ ct)
{
    int i = threadIdx.x;
    float l1 = 0.0f;
    if (i < NBOX) {
        int b = i >> 6;                       // 64 boxes per batch
        int x = ct[i * 2 + 0];
        int y = ct[i * 2 + 1];
        const float* whb = wh + (size_t)b * 2 * HhWh;
        float v0 = whb[y * Wh + x];
        float v1 = whb[HhWh + y * Wh + x];
        const float* bb = bboxes + (size_t)i * 4;
        float w = bb[2] - bb[0];
        float h = bb[3] - bb[1];
        l1 = fabsf(v0 - w) + fabsf(v1 - h);
    }
    #pragma unroll
    for (int o = 16; o > 0; o >>= 1) l1 += __shfl_xor_sync(0xffffffffu, l1, o);
    __shared__ float s[16];
    int lane = threadIdx.x & 31, wid = threadIdx.x >> 5;
    if (lane == 0) s[wid] = l1;
    __syncthreads();
    if (threadIdx.x == 0) {
        double tot = 0.0;
        #pragma unroll
        for (int k = 0; k < 16; k++) tot += (double)s[k];
        g_reg_sum = tot;
    }
}

// ---------------- combine into 4 output scalars ----------------
__global__ void combine_kernel(float* __restrict__ out) {
    // classification (OHEM)
    unsigned long long nmin = g_cnt_valid / 16ull;
    double k, top;
    if (g_cnt_hard >= nmin) {
        k = (double)g_cnt_hard;
        top = g_sum_hard;
    } else {
        k = (double)nmin;
        top = g_sum_hard;
        double need = (double)(nmin - g_cnt_hard);
        for (int bin = NBINS - 1; bin >= 0 && need > 0.0; --bin) {
            unsigned c = g_hist_cnt[bin];
            if (!c) continue;
            if ((double)c <= need) { top += g_hist_sum[bin]; need -= (double)c; }
            else                   { top += g_hist_sum[bin] * (need / (double)c); need = 0.0; }
        }
    }
    float cls = (k > 0.0) ? (float)(top / k) : 0.0f;

    // centerness (focal)
    double npos = g_npos;
    double fl = (npos == 0.0) ? -g_neg_loss
                              : -(g_pos_loss + g_neg_loss) / fmax(npos, 1.0);
    float centerness = (float)fl;

    // bbox
    float regression = (float)g_reg_sum * 0.7f;
    float bbox = regression / ((float)NBOX + 1e-7f) * 0.1f;

    float localization = (centerness + bbox) * 1.0f;

    out[0] = cls;            // classification_loss
    out[1] = localization;   // localization_loss
    out[2] = centerness;     // centerness_loss
    out[3] = bbox;           // bbox_loss
}

// ---------------- launch ----------------
extern "C" void kernel_launch(void* const* d_in, const int* in_sizes, int n_in,
                              void* d_out, int out_size)
{
    const float* seg     = (const float*)d_in[0];
    const int*   masks   = (const int*)  d_in[1];
    const float* hm_pred = (const float*)d_in[2];
    const float* hm_tgt  = (const float*)d_in[3];
    const float* wh      = (const float*)d_in[4];
    const float* bboxes  = (const float*)d_in[5];
    // d_in[6] = labels (unused by the reference loss)
    const int*   ct      = (const int*)  d_in[7];
    float* out = (float*)d_out;

    init_kernel<<<16, 256>>>();
    ohem_kernel<<<NPIX / 256, 256>>>(seg, masks);
    focal_kernel<<<NHEAT / 256, 256>>>(hm_pred, hm_tgt);
    reg_kernel<<<1, 512>>>(wh, bboxes, ct);
    combine_kernel<<<1, 1>>>(out);
}

// round 4
// speedup vs baseline: 1.0122x; 1.0122x over previous
#include <cuda_runtime.h>
#include <cstdint>

// ---------------- problem shapes (fixed by the dataset) ----------------
constexpr int B    = 8;
constexpr int C    = 19;
constexpr int H    = 512;
constexpr int W    = 1024;
constexpr int HW   = H * W;            // 524288 = 2^19
constexpr int NPIX = B * HW;           // 4194304
constexpr int Hh   = 128;
constexpr int Wh   = 256;
constexpr int HhWh = Hh * Wh;          // 32768
constexpr int NHEAT = B * HhWh;        // 262144
constexpr int NBOX  = 8 * 64;          // 512

constexpr float OHEM_THRESH = 0.22314355513142097f;  // -log(0.8)
constexpr int   NBINS = 4096;
constexpr float BIN_SCALE = (float)NBINS / OHEM_THRESH;
constexpr float F32_TINY = 1.17549435e-38f;

constexpr int THREADS      = 256;
constexpr int OHEM_BLOCKS  = NPIX / THREADS;    // 16384
constexpr int FOCAL_BLOCKS = NHEAT / THREADS;   // 1024
constexpr int TOTAL_BLOCKS = OHEM_BLOCKS + FOCAL_BLOCKS + 1;  // 17409

// ---------------- device accumulators (zero at module load; each run
// restores them to zero in the final block, keeping replays deterministic) ---
__device__ double             g_sum_hard;
__device__ unsigned long long g_cnt_hard;
__device__ unsigned long long g_cnt_valid;
__device__ double             g_hist_sum[NBINS];
__device__ unsigned int       g_hist_cnt[NBINS];
__device__ double             g_pos_loss;
__device__ double             g_neg_loss;
__device__ double             g_npos;
__device__ double             g_reg_sum;
__device__ unsigned int       g_done;

// ---------------- one fused kernel ----------------
__global__ __launch_bounds__(THREADS) void fused_loss_kernel(
    const float* __restrict__ seg,     const int*   __restrict__ masks,
    const float* __restrict__ hm_pred, const float* __restrict__ hm_tgt,
    const float* __restrict__ wh,      const float* __restrict__ bboxes,
    const int*   __restrict__ ct,      float* __restrict__ out)
{
    const int bid  = blockIdx.x;
    const int tid  = threadIdx.x;
    const int lane = tid & 31, wid = tid >> 5;

    __shared__ float    s_f0[8], s_f1[8], s_f2[8];
    __shared__ unsigned s_u0[8], s_u1[8];

    if (bid < OHEM_BLOCKS) {
        // ===================== OHEM CE =====================
        int p  = bid * THREADS + tid;
        int b  = p >> 19;                 // / HW
        int hw = p & (HW - 1);
        const float* base = seg + (size_t)b * C * HW + hw;

        int t = masks[p];
        bool valid = (t != 255);

        float v[C];
        #pragma unroll
        for (int c = 0; c < C; c++) v[c] = __ldg(base + (size_t)c * HW);

        float m = v[0];
        #pragma unroll
        for (int c = 1; c < C; c++) m = fmaxf(m, v[c]);

        float s = 0.0f, xt = v[0];
        #pragma unroll
        for (int c = 0; c < C; c++) {
            s += __expf(v[c] - m);
            xt = (c == t) ? v[c] : xt;
        }
        float ce = valid ? (m + __logf(s) - xt) : 0.0f;
        bool hard = ce > OHEM_THRESH;

        // rare path: ce <= THRESH -> global histogram (expected ~handful of hits)
        if (!hard) {
            int bin = (int)(ce * BIN_SCALE);
            bin = min(max(bin, 0), NBINS - 1);
            atomicAdd(&g_hist_cnt[bin], 1u);
            atomicAdd(&g_hist_sum[bin], (double)ce);
        }

        float fs = hard ? ce : 0.0f;
        #pragma unroll
        for (int o = 16; o > 0; o >>= 1) fs += __shfl_xor_sync(0xffffffffu, fs, o);
        unsigned bh = __ballot_sync(0xffffffffu, hard);
        unsigned bv = __ballot_sync(0xffffffffu, valid);
        if (lane == 0) { s_f0[wid] = fs; s_u0[wid] = __popc(bh); s_u1[wid] = __popc(bv); }
        __syncthreads();
        if (tid == 0) {
            double ts = 0.0; unsigned th = 0, tv = 0;
            #pragma unroll
            for (int i = 0; i < 8; i++) { ts += (double)s_f0[i]; th += s_u0[i]; tv += s_u1[i]; }
            atomicAdd(&g_sum_hard, ts);
            atomicAdd(&g_cnt_hard, (unsigned long long)th);
            atomicAdd(&g_cnt_valid, (unsigned long long)tv);
        }
    } else if (bid < OHEM_BLOCKS + FOCAL_BLOCKS) {
        // ===================== focal =====================
        int i = (bid - OHEM_BLOCKS) * THREADS + tid;
        float p = fmaxf(hm_pred[i], F32_TINY);
        float t = hm_tgt[i];
        float pl = 0.0f, nl = 0.0f, np = 0.0f;
        if (t == 1.0f) {
            float om = 1.0f - p;
            pl = __logf(p) * om * om;
            np = 1.0f;
        } else {
            float omt = 1.0f - t;
            float wgt = omt * omt; wgt *= wgt;
            nl = __logf(1.0f - p + F32_TINY) * p * p * wgt;
        }
        #pragma unroll
        for (int o = 16; o > 0; o >>= 1) {
            pl += __shfl_xor_sync(0xffffffffu, pl, o);
            nl += __shfl_xor_sync(0xffffffffu, nl, o);
            np += __shfl_xor_sync(0xffffffffu, np, o);
        }
        if (lane == 0) { s_f0[wid] = pl; s_f1[wid] = nl; s_f2[wid] = np; }
        __syncthreads();
        if (tid == 0) {
            double tp = 0, tn = 0, tc = 0;
            #pragma unroll
            for (int k = 0; k < 8; k++) { tp += (double)s_f0[k]; tn += (double)s_f1[k]; tc += (double)s_f2[k]; }
            atomicAdd(&g_pos_loss, tp);
            atomicAdd(&g_neg_loss, tn);
            atomicAdd(&g_npos, tc);
        }
    } else {
        // ===================== L1 regression (512 boxes, 2 per thread) =====================
        float l1 = 0.0f;
        #pragma unroll
        for (int r = 0; r < 2; r++) {
            int i = tid + r * THREADS;
            int b = i >> 6;
            int x = ct[i * 2 + 0];
            int y = ct[i * 2 + 1];
            const float* whb = wh + (size_t)b * 2 * HhWh;
            float v0 = whb[y * Wh + x];
            float v1 = whb[HhWh + y * Wh + x];
            const float* bb = bboxes + (size_t)i * 4;
            float w = bb[2] - bb[0];
            float h = bb[3] - bb[1];
            l1 += fabsf(v0 - w) + fabsf(v1 - h);
        }
        #pragma unroll
        for (int o = 16; o > 0; o >>= 1) l1 += __shfl_xor_sync(0xffffffffu, l1, o);
        if (lane == 0) s_f0[wid] = l1;
        __syncthreads();
        if (tid == 0) {
            double tot = 0.0;
            #pragma unroll
            for (int k = 0; k < 8; k++) tot += (double)s_f0[k];
            g_reg_sum = tot;
        }
    }

    // ===================== last-block election =====================
    __shared__ bool s_last;
    __syncthreads();            // all shared-mem reads of this block done
    if (tid == 0) {
        __threadfence();        // release our accumulator writes
        unsigned prev = atomicAdd(&g_done, 1u);
        s_last = (prev == (unsigned)(TOTAL_BLOCKS - 1));
    }
    __syncthreads();
    if (!s_last) return;
    __threadfence();            // acquire: all blocks' writes now visible

    __shared__ float s_out[4];
    if (tid == 0) {
        // classification (OHEM)
        unsigned long long nmin = g_cnt_valid / 16ull;
        double k, top;
        if (g_cnt_hard >= nmin) {
            k = (double)g_cnt_hard;
            top = g_sum_hard;
        } else {
            k = (double)nmin;
            top = g_sum_hard;
            double need = (double)(nmin - g_cnt_hard);
            for (int bin = NBINS - 1; bin >= 0 && need > 0.0; --bin) {
                unsigned c = g_hist_cnt[bin];
                if (!c) continue;
                if ((double)c <= need) { top += g_hist_sum[bin]; need -= (double)c; }
                else                   { top += g_hist_sum[bin] * (need / (double)c); need = 0.0; }
            }
        }
        float cls = (k > 0.0) ? (float)(top / k) : 0.0f;

        // centerness (focal)
        double npos = g_npos;
        double fl = (npos == 0.0) ? -g_neg_loss
                                  : -(g_pos_loss + g_neg_loss) / fmax(npos, 1.0);
        float centerness = (float)fl;

        // bbox
        float regression = (float)g_reg_sum * 0.7f;
        float bbox = regression / ((float)NBOX + 1e-7f) * 0.1f;
        float localization = (centerness + bbox) * 1.0f;

        s_out[0] = cls;
        s_out[1] = localization;
        s_out[2] = centerness;
        s_out[3] = bbox;
    }
    __syncthreads();

    // write outputs + reset all globals for the next (graph-replayed) run
    if (tid < 4) out[tid] = s_out[tid];
    for (int bin = tid; bin < NBINS; bin += THREADS) {
        g_hist_sum[bin] = 0.0;
        g_hist_cnt[bin] = 0u;
    }
    if (tid == 0) {
        g_sum_hard = 0.0; g_cnt_hard = 0ull; g_cnt_valid = 0ull;
        g_pos_loss = 0.0; g_neg_loss = 0.0; g_npos = 0.0; g_reg_sum = 0.0;
        __threadfence();
        g_done = 0u;
    }
}

// ---------------- launch ----------------
extern "C" void kernel_launch(void* const* d_in, const int* in_sizes, int n_in,
                              void* d_out, int out_size)
{
    const float* seg     = (const float*)d_in[0];
    const int*   masks   = (const int*)  d_in[1];
    const float* hm_pred = (const float*)d_in[2];
    const float* hm_tgt  = (const float*)d_in[3];
    const float* wh      = (const float*)d_in[4];
    const float* bboxes  = (const float*)d_in[5];
    // d_in[6] = labels (unused by the reference loss)
    const int*   ct      = (const int*)  d_in[7];
    float* out = (float*)d_out;

    fused_loss_kernel<<<TOTAL_BLOCKS, THREADS>>>(
        seg, masks, hm_pred, hm_tgt, wh, bboxes, ct, out);
}

// round 5
// speedup vs baseline: 1.0825x; 1.0695x over previous
#include <cuda_runtime.h>
#include <cstdint>

// ---------------- problem shapes (fixed by the dataset) ----------------
constexpr int B    = 8;
constexpr int C    = 19;
constexpr int H    = 512;
constexpr int W    = 1024;
constexpr int HW   = H * W;            // 524288 = 2^19
constexpr int NPIX = B * HW;           // 4194304
constexpr int Hh   = 128;
constexpr int Wh   = 256;
constexpr int HhWh = Hh * Wh;          // 32768
constexpr int NHEAT = B * HhWh;        // 262144
constexpr int NBOX  = 8 * 64;          // 512

constexpr float OHEM_THRESH = 0.22314355513142097f;  // -log(0.8)
constexpr int   NBINS = 4096;
constexpr float BIN_SCALE = (float)NBINS / OHEM_THRESH;
constexpr float F32_TINY = 1.17549435e-38f;
constexpr float L2E  = 1.4426950408889634f;   // log2(e)
constexpr float LN2  = 0.6931471805599453f;   // ln(2)

constexpr int THREADS      = 256;
constexpr int PIXPAIRS     = NPIX / 2;                    // 2097152
constexpr int OHEM_BLOCKS  = PIXPAIRS / THREADS;          // 8192
constexpr int FOCAL_BLOCKS = NHEAT / (THREADS * 4);       // 256
constexpr int TOTAL_BLOCKS = OHEM_BLOCKS + FOCAL_BLOCKS + 1;  // 8449

// ---------------- device accumulators (zero at load; final block re-zeros
// them each run so graph replays stay deterministic) ----------------
__device__ double             g_sum_hard;
__device__ unsigned long long g_cnt_hard;
__device__ unsigned long long g_cnt_valid;
__device__ double             g_hist_sum[NBINS];
__device__ unsigned int       g_hist_cnt[NBINS];
__device__ double             g_pos_loss;
__device__ double             g_neg_loss;
__device__ double             g_npos;
__device__ double             g_reg_sum;
__device__ unsigned int       g_done;

__device__ __forceinline__ float ex2f(float x) {
    float r;
    asm("ex2.approx.ftz.f32 %0, %1;" : "=f"(r) : "f"(x));
    return r;
}
__device__ __forceinline__ float lg2f(float x) {
    float r;
    asm("lg2.approx.ftz.f32 %0, %1;" : "=f"(r) : "f"(x));
    return r;
}

// ---------------- one fused kernel ----------------
__global__ __launch_bounds__(THREADS) void fused_loss_kernel(
    const float* __restrict__ seg,     const int*   __restrict__ masks,
    const float* __restrict__ hm_pred, const float* __restrict__ hm_tgt,
    const float* __restrict__ wh,      const float* __restrict__ bboxes,
    const int*   __restrict__ ct,      float* __restrict__ out)
{
    const int bid  = blockIdx.x;
    const int tid  = threadIdx.x;
    const int lane = tid & 31, wid = tid >> 5;

    __shared__ float    s_f0[8], s_f1[8], s_f2[8];
    __shared__ unsigned s_u0[8], s_u1[8];

    if (bid < OHEM_BLOCKS) {
        // ============ OHEM CE: 2 pixels per thread via float2 ============
        int q  = bid * THREADS + tid;          // pair index
        int b  = q >> 18;                      // / (HW/2)
        int hp = q & (HW / 2 - 1);             // pair offset within image
        const float* img = seg + (size_t)b * C * HW;   // this batch's logits
        const float2* base2 = (const float2*)img + hp;

        int2 tt = __ldg((const int2*)masks + q);
        bool valid0 = (tt.x != 255), valid1 = (tt.y != 255);
        int t0 = valid0 ? tt.x : 0;
        int t1 = valid1 ? tt.y : 0;

        float2 v[C];
        #pragma unroll
        for (int c = 0; c < C; c++) v[c] = __ldg(base2 + (size_t)c * (HW / 2));

        float m0 = v[0].x, m1 = v[0].y;
        #pragma unroll
        for (int c = 1; c < C; c++) {
            m0 = fmaxf(m0, v[c].x);
            m1 = fmaxf(m1, v[c].y);
        }

        float nm0 = -m0 * L2E, nm1 = -m1 * L2E;
        float s0 = 0.0f, s1 = 0.0f;
        #pragma unroll
        for (int c = 0; c < C; c++) {
            s0 += ex2f(__fmaf_rn(v[c].x, L2E, nm0));
            s1 += ex2f(__fmaf_rn(v[c].y, L2E, nm1));
        }

        // target logit via direct (L1-hit) load — replaces 19-deep select chain
        int hw0 = hp * 2;
        float xt0 = __ldg(img + (size_t)t0 * HW + hw0);
        float xt1 = __ldg(img + (size_t)t1 * HW + hw0 + 1);

        float ce0 = valid0 ? (__fmaf_rn(lg2f(s0), LN2, m0) - xt0) : 0.0f;
        float ce1 = valid1 ? (__fmaf_rn(lg2f(s1), LN2, m1) - xt1) : 0.0f;

        bool hard0 = ce0 > OHEM_THRESH;
        bool hard1 = ce1 > OHEM_THRESH;

        // rare path: ce <= THRESH -> global histogram (expected ~handful of hits)
        if (!hard0) {
            int bin = min(max((int)(ce0 * BIN_SCALE), 0), NBINS - 1);
            atomicAdd(&g_hist_cnt[bin], 1u);
            atomicAdd(&g_hist_sum[bin], (double)ce0);
        }
        if (!hard1) {
            int bin = min(max((int)(ce1 * BIN_SCALE), 0), NBINS - 1);
            atomicAdd(&g_hist_cnt[bin], 1u);
            atomicAdd(&g_hist_sum[bin], (double)ce1);
        }

        float    fs = (hard0 ? ce0 : 0.0f) + (hard1 ? ce1 : 0.0f);
        unsigned hc = (unsigned)hard0 + (unsigned)hard1;
        unsigned vc = (unsigned)valid0 + (unsigned)valid1;
        #pragma unroll
        for (int o = 16; o > 0; o >>= 1) {
            fs += __shfl_xor_sync(0xffffffffu, fs, o);
            hc += __shfl_xor_sync(0xffffffffu, hc, o);
            vc += __shfl_xor_sync(0xffffffffu, vc, o);
        }
        if (lane == 0) { s_f0[wid] = fs; s_u0[wid] = hc; s_u1[wid] = vc; }
        __syncthreads();
        if (tid == 0) {
            double ts = 0.0; unsigned th = 0, tv = 0;
            #pragma unroll
            for (int i = 0; i < 8; i++) { ts += (double)s_f0[i]; th += s_u0[i]; tv += s_u1[i]; }
            atomicAdd(&g_sum_hard, ts);
            atomicAdd(&g_cnt_hard, (unsigned long long)th);
            atomicAdd(&g_cnt_valid, (unsigned long long)tv);
        }
    } else if (bid < OHEM_BLOCKS + FOCAL_BLOCKS) {
        // ============ focal: 4 elems per thread via float4 ============
        int i4 = (bid - OHEM_BLOCKS) * THREADS + tid;
        float4 pv = __ldg((const float4*)hm_pred + i4);
        float4 tv4 = __ldg((const float4*)hm_tgt + i4);

        float pl = 0.0f, nl = 0.0f, np = 0.0f;
        const float* pp = &pv.x;
        const float* tp = &tv4.x;
        #pragma unroll
        for (int k = 0; k < 4; k++) {
            float p = fmaxf(pp[k], F32_TINY);
            float t = tp[k];
            if (t == 1.0f) {
                float om = 1.0f - p;
                pl += lg2f(p) * LN2 * om * om;
                np += 1.0f;
            } else {
                float omt = 1.0f - t;
                float wgt = omt * omt; wgt *= wgt;
                nl += lg2f(1.0f - p + F32_TINY) * LN2 * p * p * wgt;
            }
        }
        #pragma unroll
        for (int o = 16; o > 0; o >>= 1) {
            pl += __shfl_xor_sync(0xffffffffu, pl, o);
            nl += __shfl_xor_sync(0xffffffffu, nl, o);
            np += __shfl_xor_sync(0xffffffffu, np, o);
        }
        if (lane == 0) { s_f0[wid] = pl; s_f1[wid] = nl; s_f2[wid] = np; }
        __syncthreads();
        if (tid == 0) {
            double tpd = 0, tnd = 0, tcd = 0;
            #pragma unroll
            for (int k = 0; k < 8; k++) { tpd += (double)s_f0[k]; tnd += (double)s_f1[k]; tcd += (double)s_f2[k]; }
            atomicAdd(&g_pos_loss, tpd);
            atomicAdd(&g_neg_loss, tnd);
            atomicAdd(&g_npos, tcd);
        }
    } else {
        // ============ L1 regression (512 boxes, 2 per thread) ============
        float l1 = 0.0f;
        #pragma unroll
        for (int r = 0; r < 2; r++) {
            int i = tid + r * THREADS;
            int b = i >> 6;
            int x = ct[i * 2 + 0];
            int y = ct[i * 2 + 1];
            const float* whb = wh + (size_t)b * 2 * HhWh;
            float v0 = whb[y * Wh + x];
            float v1 = whb[HhWh + y * Wh + x];
            const float* bb = bboxes + (size_t)i * 4;
            float w = bb[2] - bb[0];
            float h = bb[3] - bb[1];
            l1 += fabsf(v0 - w) + fabsf(v1 - h);
        }
        #pragma unroll
        for (int o = 16; o > 0; o >>= 1) l1 += __shfl_xor_sync(0xffffffffu, l1, o);
        if (lane == 0) s_f0[wid] = l1;
        __syncthreads();
        if (tid == 0) {
            double tot = 0.0;
            #pragma unroll
            for (int k = 0; k < 8; k++) tot += (double)s_f0[k];
            g_reg_sum = tot;
        }
    }

    // ===================== last-block election =====================
    __shared__ bool s_last;
    __syncthreads();
    if (tid == 0) {
        __threadfence();
        unsigned prev = atomicAdd(&g_done, 1u);
        s_last = (prev == (unsigned)(TOTAL_BLOCKS - 1));
    }
    __syncthreads();
    if (!s_last) return;
    __threadfence();

    __shared__ float s_out[4];
    if (tid == 0) {
        // classification (OHEM)
        unsigned long long nmin = g_cnt_valid / 16ull;
        double k, top;
        if (g_cnt_hard >= nmin) {
            k = (double)g_cnt_hard;
            top = g_sum_hard;
        } else {
            k = (double)nmin;
            top = g_sum_hard;
            double need = (double)(nmin - g_cnt_hard);
            for (int bin = NBINS - 1; bin >= 0 && need > 0.0; --bin) {
                unsigned c = g_hist_cnt[bin];
                if (!c) continue;
                if ((double)c <= need) { top += g_hist_sum[bin]; need -= (double)c; }
                else                   { top += g_hist_sum[bin] * (need / (double)c); need = 0.0; }
            }
        }
        float cls = (k > 0.0) ? (float)(top / k) : 0.0f;

        // centerness (focal)
        double npos = g_npos;
        double fl = (npos == 0.0) ? -g_neg_loss
                                  : -(g_pos_loss + g_neg_loss) / fmax(npos, 1.0);
        float centerness = (float)fl;

        // bbox
        float regression = (float)g_reg_sum * 0.7f;
        float bbox = regression / ((float)NBOX + 1e-7f) * 0.1f;
        float localization = (centerness + bbox) * 1.0f;

        s_out[0] = cls;
        s_out[1] = localization;
        s_out[2] = centerness;
        s_out[3] = bbox;
    }
    __syncthreads();

    if (tid < 4) out[tid] = s_out[tid];
    for (int bin = tid; bin < NBINS; bin += THREADS) {
        g_hist_sum[bin] = 0.0;
        g_hist_cnt[bin] = 0u;
    }
    if (tid == 0) {
        g_sum_hard = 0.0; g_cnt_hard = 0ull; g_cnt_valid = 0ull;
        g_pos_loss = 0.0; g_neg_loss = 0.0; g_npos = 0.0; g_reg_sum = 0.0;
        __threadfence();
        g_done = 0u;
    }
}

// ---------------- launch ----------------
extern "C" void kernel_launch(void* const* d_in, const int* in_sizes, int n_in,
                              void* d_out, int out_size)
{
    const float* seg     = (const float*)d_in[0];
    const int*   masks   = (const int*)  d_in[1];
    const float* hm_pred = (const float*)d_in[2];
    const float* hm_tgt  = (const float*)d_in[3];
    const float* wh      = (const float*)d_in[4];
    const float* bboxes  = (const float*)d_in[5];
    // d_in[6] = labels (unused by the reference loss)
    const int*   ct      = (const int*)  d_in[7];
    float* out = (float*)d_out;

    fused_loss_kernel<<<TOTAL_BLOCKS, THREADS>>>(
        seg, masks, hm_pred, hm_tgt, wh, bboxes, ct, out);
}